// round 14
// baseline (speedup 1.0000x reference)
#include <cuda_runtime.h>
#include <cuda_bf16.h>
#include <cuda_fp16.h>
#include <cstdint>

#define BATCH 8
#define NPTS  4096
#define DIM   256

// tile geometry
#define TILE_N 256            // X rows per CTA (gemm M)
#define TILE_M 128            // Y rows per m-tile (gemm N)
#define MT     4              // m-tiles per CTA
#define KCH    32             // K fp16 elements per k-chunk
#define NSTG   8              // DIM / KCH
#define TOTSTG (MT * NSTG)    // 32

// smem layout: A resident (8 chunks x 256 rows x 80B) + 4 B buffers (128 x 80B)
#define A_CHUNK_BYTES (TILE_N * 80)        // 20480
#define A_TOTAL       (8 * A_CHUNK_BYTES)  // 163840
#define B_BUF_BYTES   (TILE_M * 80)        // 10240
#define B_OFF         A_TOTAL
#define SMEM_BYTES    (A_TOTAL + 4 * B_BUF_BYTES)  // 204800

// ---------------- scratch globals ----------------
__device__ unsigned g_min_n[BATCH * NPTS];
__device__ unsigned g_min_m[BATCH * NPTS];
__device__ float    g_xx[BATCH * NPTS];
__device__ float    g_yy[BATCH * NPTS];
__device__ __half   g_xh[BATCH * NPTS * DIM];   // 16 MB
__device__ __half   g_yh[BATCH * NPTS * DIM];   // 16 MB
__device__ unsigned g_done;                      // zero-init; self-resetting

__device__ __forceinline__ unsigned f2ord(float f) {
    unsigned u = __float_as_uint(f);
    return (u & 0x80000000u) ? ~u : (u ^ 0x80000000u);
}
__device__ __forceinline__ float ord2f(unsigned u) {
    u = (u & 0x80000000u) ? (u ^ 0x80000000u) : ~u;
    return __uint_as_float(u);
}

__device__ __forceinline__ uint32_t smem_u32(const void* p) {
    uint32_t a;
    asm("{ .reg .u64 t; cvta.to.shared.u64 t, %1; cvt.u32.u64 %0, t; }" : "=r"(a) : "l"(p));
    return a;
}
__device__ __forceinline__ void cpasync16(uint32_t dst, const void* src) {
    asm volatile("cp.async.cg.shared.global [%0], [%1], 16;" :: "r"(dst), "l"(src));
}
#define CP_COMMIT() asm volatile("cp.async.commit_group;" ::: "memory")
#define CP_WAIT2()  asm volatile("cp.async.wait_group 2;" ::: "memory")

#define LDSM_X4(r, a) \
    asm volatile("ldmatrix.sync.aligned.m8n8.x4.shared.b16 {%0,%1,%2,%3}, [%4];" \
        : "=r"((r)[0]), "=r"((r)[1]), "=r"((r)[2]), "=r"((r)[3]) : "r"(a))

__device__ __forceinline__ void mma_f16(float& d0, float& d1, float& d2, float& d3,
                                        uint32_t a0, uint32_t a1, uint32_t a2, uint32_t a3,
                                        uint32_t b0, uint32_t b1) {
    asm volatile(
        "mma.sync.aligned.m16n8k16.row.col.f32.f16.f16.f32 "
        "{%0,%1,%2,%3}, {%4,%5,%6,%7}, {%8,%9}, {%0,%1,%2,%3};"
        : "+f"(d0), "+f"(d1), "+f"(d2), "+f"(d3)
        : "r"(a0), "r"(a1), "r"(a2), "r"(a3), "r"(b0), "r"(b1));
}

// ---------------------------------------------------------------------------
// Kernel 1: row norms + min init + fp32 -> fp16 conversion (one warp per row)
// ---------------------------------------------------------------------------
__global__ void norms_init_kernel(const float* __restrict__ X,
                                  const float* __restrict__ Y) {
    int warp = (blockIdx.x * blockDim.x + threadIdx.x) >> 5;
    int lane = threadIdx.x & 31;
    const float* src = (blockIdx.y == 0) ? X : Y;
    float*    dst_n  = (blockIdx.y == 0) ? g_xx : g_yy;
    unsigned* dst_mn = (blockIdx.y == 0) ? g_min_n : g_min_m;
    __half*   dst_h  = (blockIdx.y == 0) ? g_xh : g_yh;

    const float4* row = (const float4*)(src + (size_t)warp * DIM);
    float4 a = row[lane];
    float4 b = row[lane + 32];

    __half2* hrow = (__half2*)(dst_h + (size_t)warp * DIM);
    hrow[lane * 2 + 0]      = __floats2half2_rn(a.x, a.y);
    hrow[lane * 2 + 1]      = __floats2half2_rn(a.z, a.w);
    hrow[64 + lane * 2 + 0] = __floats2half2_rn(b.x, b.y);
    hrow[64 + lane * 2 + 1] = __floats2half2_rn(b.z, b.w);

    float s = a.x * a.x + a.y * a.y + a.z * a.z + a.w * a.w
            + b.x * b.x + b.y * b.y + b.z * b.z + b.w * b.w;
#pragma unroll
    for (int off = 16; off > 0; off >>= 1)
        s += __shfl_xor_sync(0xFFFFFFFFu, s, off);
    if (lane == 0) {
        dst_n[warp]  = s;
        dst_mn[warp] = 0xFFFFFFFFu;
    }
}

// ---------------------------------------------------------------------------
// Kernel 2: fp16 mma.sync + ldmatrix, A-resident smem, fused finalize.
// CTA = 256(n) x 4 tiles of 128(m). grid: (8, 16, BATCH), 512 threads
// ---------------------------------------------------------------------------
__global__ __launch_bounds__(512, 1)
void chamfer_mma_kernel(float* __restrict__ out) {
    extern __shared__ __align__(16) char smem[];
    const uint32_t sb = smem_u32(smem);

    const int tid  = threadIdx.x;
    const int wid  = tid >> 5;
    const int lane = tid & 31;
    const int r4   = lane >> 2;   // 0..7
    const int c4   = lane & 3;    // 0..3
    const int wn   = wid >> 2;    // warp n-group: 64 rows
    const int wm   = wid & 3;     // warp m-group: 32 cols

    const int b     = blockIdx.z;
    const int n0    = blockIdx.y * TILE_N;
    const int m0bas = blockIdx.x * (TILE_M * MT);

    const __half* xb = g_xh + ((size_t)b * NPTS + n0) * DIM;
    const __half* yb = g_yh + ((size_t)b * NPTS + m0bas) * DIM;

    // per-lane ldmatrix offsets (bytes)
    const uint32_t a_off = (uint32_t)((wn * 64 + (lane & 15)) * 80
                                      + ((lane >> 4) & 1) * 16);
    const uint32_t b_off = (uint32_t)(B_OFF
                         + (wm * 32 + (lane >> 4) * 8 + (lane & 7)) * 80
                         + ((lane >> 3) & 1) * 16);

    // ---- prologue: load ALL of A (8 k-chunks), resident for whole CTA ----
    // 8192 16B-chunks over 512 threads = 16 each
#pragma unroll
    for (int i = 0; i < 16; ++i) {
        int cid = tid + i * 512;            // 0..8191
        int kc  = cid >> 10;                // k-chunk 0..7
        int rem = cid & 1023;
        int row = rem >> 2, q = rem & 3;
        cpasync16(sb + (uint32_t)(kc * A_CHUNK_BYTES + row * 80 + q * 16),
                  xb + (size_t)row * DIM + kc * KCH + q * 8);
    }

    // ---- B stage loader: stage g covers m-tile g>>3, k-chunk g&7 ----
    auto load_B = [&](int g) {
        const uint32_t base = sb + B_OFF + (uint32_t)(g & 3) * B_BUF_BYTES;
        const __half* ybt = yb + (size_t)(g >> 3) * TILE_M * DIM;
        int row = tid >> 2, q = tid & 3;
        cpasync16(base + (uint32_t)(row * 80 + q * 16),
                  ybt + (size_t)row * DIM + (g & 7) * KCH + q * 8);
    };

    load_B(0); CP_COMMIT();   // group: A + B0
    load_B(1); CP_COMMIT();
    load_B(2); CP_COMMIT();

    float acc[4][4][4];
#pragma unroll
    for (int fi = 0; fi < 4; ++fi)
#pragma unroll
        for (int fj = 0; fj < 4; ++fj)
#pragma unroll
            for (int q = 0; q < 4; ++q) acc[fi][fj][q] = 0.f;

    const float INF = 3.402823466e38f;
    float rmin[8], xr[8];
#pragma unroll
    for (int i = 0; i < 8; ++i) rmin[i] = INF;
#pragma unroll
    for (int fi = 0; fi < 4; ++fi) {
        int r0 = b * NPTS + n0 + wn * 64 + fi * 16 + r4;
        xr[fi * 2 + 0] = g_xx[r0];
        xr[fi * 2 + 1] = g_xx[r0 + 8];
    }

#pragma unroll 1
    for (int g = 0; g < TOTSTG; ++g) {
        CP_WAIT2();
        __syncthreads();

        const uint32_t a_base = sb + (uint32_t)(g & 7) * A_CHUNK_BYTES + a_off;
        const uint32_t b_base = sb + (uint32_t)(g & 3) * B_BUF_BYTES + b_off
                                - B_OFF + B_OFF;  // keep b_off absolute
        const uint32_t b_base2 = sb + b_off + (uint32_t)(g & 3) * B_BUF_BYTES;

#pragma unroll
        for (int k16 = 0; k16 < 2; ++k16) {
            const uint32_t kb = k16 * 32;
            uint32_t af[4][4], bf0[4], bf1[4];
            LDSM_X4(bf0, b_base2 + kb);
            LDSM_X4(bf1, b_base2 + 16 * 80 + kb);
#pragma unroll
            for (int fi = 0; fi < 4; ++fi)
                LDSM_X4(af[fi], a_base + fi * 16 * 80 + kb);
#pragma unroll
            for (int fi = 0; fi < 4; ++fi) {
                mma_f16(acc[fi][0][0], acc[fi][0][1], acc[fi][0][2], acc[fi][0][3],
                        af[fi][0], af[fi][1], af[fi][2], af[fi][3], bf0[0], bf0[1]);
                mma_f16(acc[fi][1][0], acc[fi][1][1], acc[fi][1][2], acc[fi][1][3],
                        af[fi][0], af[fi][1], af[fi][2], af[fi][3], bf0[2], bf0[3]);
                mma_f16(acc[fi][2][0], acc[fi][2][1], acc[fi][2][2], acc[fi][2][3],
                        af[fi][0], af[fi][1], af[fi][2], af[fi][3], bf1[0], bf1[1]);
                mma_f16(acc[fi][3][0], acc[fi][3][1], acc[fi][3][2], acc[fi][3][3],
                        af[fi][0], af[fi][1], af[fi][2], af[fi][3], bf1[2], bf1[3]);
            }
        }

        if (g + 3 < TOTSTG) load_B(g + 3);
        CP_COMMIT();

        // ---- per-tile epilogue (register-only; overlaps in-flight cp.async) ----
        if ((g & 7) == 7) {
            const int m0t = m0bas + (g >> 3) * TILE_M;

            float yc[8];
#pragma unroll
            for (int fj = 0; fj < 4; ++fj) {
                int c0 = b * NPTS + m0t + wm * 32 + fj * 8 + 2 * c4;
                yc[fj * 2 + 0] = g_yy[c0];
                yc[fj * 2 + 1] = g_yy[c0 + 1];
            }

            float cmin[8];
#pragma unroll
            for (int i = 0; i < 8; ++i) cmin[i] = INF;

#pragma unroll
            for (int fi = 0; fi < 4; ++fi)
#pragma unroll
                for (int fj = 0; fj < 4; ++fj)
#pragma unroll
                    for (int r = 0; r < 2; ++r)
#pragma unroll
                        for (int c = 0; c < 2; ++c) {
                            float d = xr[fi * 2 + r] + yc[fj * 2 + c]
                                    - 2.0f * acc[fi][fj][2 * r + c];
                            rmin[fi * 2 + r] = fminf(rmin[fi * 2 + r], d);
                            cmin[fj * 2 + c] = fminf(cmin[fj * 2 + c], d);
                            acc[fi][fj][2 * r + c] = 0.f;
                        }

#pragma unroll
            for (int i = 0; i < 8; ++i) {
                cmin[i] = fminf(cmin[i], __shfl_xor_sync(0xFFFFFFFFu, cmin[i], 4));
                cmin[i] = fminf(cmin[i], __shfl_xor_sync(0xFFFFFFFFu, cmin[i], 8));
                cmin[i] = fminf(cmin[i], __shfl_xor_sync(0xFFFFFFFFu, cmin[i], 16));
            }
            if (r4 == 0) {
#pragma unroll
                for (int fj = 0; fj < 4; ++fj)
#pragma unroll
                    for (int c = 0; c < 2; ++c) {
                        int col = m0t + wm * 32 + fj * 8 + 2 * c4 + c;
                        atomicMin(&g_min_m[b * NPTS + col], f2ord(cmin[fj * 2 + c]));
                    }
            }
        }
    }

    // ---- final row-min flush ----
#pragma unroll
    for (int i = 0; i < 8; ++i) {
        rmin[i] = fminf(rmin[i], __shfl_xor_sync(0xFFFFFFFFu, rmin[i], 1));
        rmin[i] = fminf(rmin[i], __shfl_xor_sync(0xFFFFFFFFu, rmin[i], 2));
    }
    if (c4 == 0) {
#pragma unroll
        for (int fi = 0; fi < 4; ++fi)
#pragma unroll
            for (int r = 0; r < 2; ++r) {
                int row = n0 + wn * 64 + fi * 16 + 8 * r + r4;
                atomicMin(&g_min_n[b * NPTS + row], f2ord(rmin[fi * 2 + r]));
            }
    }

    // ---- fused finalize: last CTA reduces both min arrays to out[0] ----
    __shared__ unsigned s_last;
    __shared__ double   s_red[16];
    __threadfence();
    __syncthreads();
    if (tid == 0) {
        unsigned old = atomicAdd(&g_done, 1u);
        s_last = (old == (8u * 16u * BATCH - 1u)) ? 1u : 0u;
    }
    __syncthreads();
    if (s_last) {
        const int total = BATCH * NPTS;
        double s = 0.0;
        for (int i = tid; i < total; i += 512) s += (double)ord2f(__ldcg(&g_min_n[i]));
        for (int i = tid; i < total; i += 512) s += (double)ord2f(__ldcg(&g_min_m[i]));
#pragma unroll
        for (int off = 16; off > 0; off >>= 1)
            s += __shfl_xor_sync(0xFFFFFFFFu, s, off);
        if (lane == 0) s_red[wid] = s;
        __syncthreads();
        if (tid == 0) {
            double t = 0.0;
#pragma unroll
            for (int w = 0; w < 16; ++w) t += s_red[w];
            out[0] = (float)t;
            g_done = 0;   // reset for next graph replay
        }
    }
}

extern "C" void kernel_launch(void* const* d_in, const int* in_sizes, int n_in,
                              void* d_out, int out_size) {
    const float* gts   = (const float*)d_in[0];
    const float* preds = (const float*)d_in[1];
    float* out = (float*)d_out;

    cudaFuncSetAttribute(chamfer_mma_kernel,
                         cudaFuncAttributeMaxDynamicSharedMemorySize, SMEM_BYTES);

    dim3 gN((BATCH * NPTS) / 8, 2);
    norms_init_kernel<<<gN, 256>>>(gts, preds);

    dim3 gT(NPTS / (TILE_M * MT), NPTS / TILE_N, BATCH);
    chamfer_mma_kernel<<<gT, 512, SMEM_BYTES>>>(out);
}

// round 16
// speedup vs baseline: 1.0954x; 1.0954x over previous
#include <cuda_runtime.h>
#include <cuda_bf16.h>
#include <cuda_fp16.h>
#include <cstdint>

#define BATCH 8
#define NPTS  4096
#define DIM   256

#define TILE_N 256            // X rows per CTA
#define TILE_M 128            // Y rows per m-tile
#define MT     4              // m-tiles per CTA
#define KCH    32             // K halfs per k-chunk
#define TOTSTG 32             // MT * 8

// A resident: 8 k-chunks x 256 rows x 64B (swizzled)
#define A_CHUNK 16384
#define A_TOTAL (8 * A_CHUNK)              // 131072
// B: per-group private ring: 4 groups x 4 bufs x 2KB
#define B_OFF   A_TOTAL
#define B_GRP   8192
#define B_BUF   2048
#define SMEM_BYTES (A_TOTAL + 4 * B_GRP)   // 163840

// ---------------- scratch globals ----------------
__device__ unsigned g_min_n[BATCH * NPTS];
__device__ unsigned g_min_m[BATCH * NPTS];
__device__ float    g_xx[BATCH * NPTS];
__device__ float    g_yy[BATCH * NPTS];
__device__ __half   g_xh[BATCH * NPTS * DIM];
__device__ __half   g_yh[BATCH * NPTS * DIM];
__device__ unsigned g_done;

__device__ __forceinline__ unsigned f2ord(float f) {
    unsigned u = __float_as_uint(f);
    return (u & 0x80000000u) ? ~u : (u ^ 0x80000000u);
}
__device__ __forceinline__ float ord2f(unsigned u) {
    u = (u & 0x80000000u) ? (u ^ 0x80000000u) : ~u;
    return __uint_as_float(u);
}
__device__ __forceinline__ uint32_t smem_u32(const void* p) {
    uint32_t a;
    asm("{ .reg .u64 t; cvta.to.shared.u64 t, %1; cvt.u32.u64 %0, t; }" : "=r"(a) : "l"(p));
    return a;
}
__device__ __forceinline__ void cpasync16(uint32_t dst, const void* src) {
    asm volatile("cp.async.cg.shared.global [%0], [%1], 16;" :: "r"(dst), "l"(src));
}
#define CP_COMMIT() asm volatile("cp.async.commit_group;" ::: "memory")
#define CP_WAIT2()  asm volatile("cp.async.wait_group 2;" ::: "memory")
#define GRP_BAR(id) asm volatile("bar.sync %0, 128;" :: "r"(id) : "memory")

#define LDSM_X4(r, a) \
    asm volatile("ldmatrix.sync.aligned.m8n8.x4.shared.b16 {%0,%1,%2,%3}, [%4];" \
        : "=r"((r)[0]), "=r"((r)[1]), "=r"((r)[2]), "=r"((r)[3]) : "r"(a))

__device__ __forceinline__ void mma_f16(float& d0, float& d1, float& d2, float& d3,
                                        uint32_t a0, uint32_t a1, uint32_t a2, uint32_t a3,
                                        uint32_t b0, uint32_t b1) {
    asm volatile(
        "mma.sync.aligned.m16n8k16.row.col.f32.f16.f16.f32 "
        "{%0,%1,%2,%3}, {%4,%5,%6,%7}, {%8,%9}, {%0,%1,%2,%3};"
        : "+f"(d0), "+f"(d1), "+f"(d2), "+f"(d3)
        : "r"(a0), "r"(a1), "r"(a2), "r"(a3), "r"(b0), "r"(b1));
}

// swizzle: 64B rows, 4x16B chunks; chunk c at physical (c ^ ((row>>1)&3))
__device__ __forceinline__ uint32_t swz(int row, int c) {
    return (uint32_t)(row * 64 + ((c ^ ((row >> 1) & 3)) << 4));
}

// ---------------------------------------------------------------------------
// Kernel 1: row norms + min init + fp16 conversion (one warp per row)
// ---------------------------------------------------------------------------
__global__ void norms_init_kernel(const float* __restrict__ X,
                                  const float* __restrict__ Y) {
    int warp = (blockIdx.x * blockDim.x + threadIdx.x) >> 5;
    int lane = threadIdx.x & 31;
    const float* src = (blockIdx.y == 0) ? X : Y;
    float*    dst_n  = (blockIdx.y == 0) ? g_xx : g_yy;
    unsigned* dst_mn = (blockIdx.y == 0) ? g_min_n : g_min_m;
    __half*   dst_h  = (blockIdx.y == 0) ? g_xh : g_yh;

    const float4* row = (const float4*)(src + (size_t)warp * DIM);
    float4 a = row[lane];
    float4 b = row[lane + 32];

    __half2* hrow = (__half2*)(dst_h + (size_t)warp * DIM);
    hrow[lane * 2 + 0]      = __floats2half2_rn(a.x, a.y);
    hrow[lane * 2 + 1]      = __floats2half2_rn(a.z, a.w);
    hrow[64 + lane * 2 + 0] = __floats2half2_rn(b.x, b.y);
    hrow[64 + lane * 2 + 1] = __floats2half2_rn(b.z, b.w);

    float s = a.x * a.x + a.y * a.y + a.z * a.z + a.w * a.w
            + b.x * b.x + b.y * b.y + b.z * b.z + b.w * b.w;
#pragma unroll
    for (int off = 16; off > 0; off >>= 1)
        s += __shfl_xor_sync(0xFFFFFFFFu, s, off);
    if (lane == 0) {
        dst_n[warp]  = s;
        dst_mn[warp] = 0xFFFFFFFFu;
    }
}

// ---------------------------------------------------------------------------
// Kernel 2: 4 decoupled warp-groups, each with private B ring + named barrier.
// wn = wid&3 (A rows), wm = wid>>2 = group id (B cols, contiguous 128 threads).
// ---------------------------------------------------------------------------
__global__ __launch_bounds__(512, 1)
void chamfer_mma_kernel(float* __restrict__ out) {
    extern __shared__ __align__(16) char smem[];
    const uint32_t sb = smem_u32(smem);

    const int tid  = threadIdx.x;
    const int wid  = tid >> 5;
    const int lane = tid & 31;
    const int r4   = lane >> 2;
    const int c4   = lane & 3;
    const int wn   = wid & 3;     // A row group (64 rows)
    const int wm   = wid >> 2;    // B col group == warp-group id
    const int grp  = wm;
    const int tig  = tid & 127;   // thread-in-group

    const int b     = blockIdx.z;
    const int n0    = blockIdx.y * TILE_N;
    const int m0bas = blockIdx.x * (TILE_M * MT);

    const __half* xb = g_xh + ((size_t)b * NPTS + n0) * DIM;
    const __half* yb = g_yh + ((size_t)b * NPTS + m0bas) * DIM;

    // ---- per-lane ldmatrix constants ----
    const int lhA = (lane >> 4) & 1;
    const int swA = ((lane & 15) >> 1) & 3;
    const uint32_t a_lane_base = (uint32_t)((wn * 64 + (lane & 15)) * 64);
    uint32_t aoff[2];
    aoff[0] = (uint32_t)(((0 * 2 + lhA) ^ swA) << 4);
    aoff[1] = (uint32_t)(((1 * 2 + lhA) ^ swA) << 4);

    const int rowB = (lane >> 4) * 8 + (lane & 7);   // 0..15
    const int lhB  = (lane >> 3) & 1;
    const int swB  = (rowB >> 1) & 3;
    const uint32_t b_lane_base = (uint32_t)(rowB * 64);
    uint32_t boff[2];
    boff[0] = (uint32_t)(((0 * 2 + lhB) ^ swB) << 4);
    boff[1] = (uint32_t)(((1 * 2 + lhB) ^ swB) << 4);

    // ---- prologue: all of A (swizzled, 64B rows), group's B0..B2 ----
#pragma unroll
    for (int i = 0; i < 16; ++i) {
        int cid = tid + i * 512;            // 0..8191
        int kc  = cid >> 10;
        int rem = cid & 1023;
        int row = rem >> 2, q = rem & 3;
        cpasync16(sb + (uint32_t)kc * A_CHUNK + swz(row, q),
                  xb + (size_t)row * DIM + kc * KCH + q * 8);
    }

    auto load_B = [&](int g) {
        const uint32_t base = sb + B_OFF + (uint32_t)grp * B_GRP
                            + (uint32_t)(g & 3) * B_BUF;
        const __half* ybt = yb + (size_t)(g >> 3) * TILE_M * DIM;
        int row = tig >> 2, q = tig & 3;    // 32 rows x 4 chunks
        cpasync16(base + swz(row, q),
                  ybt + (size_t)(grp * 32 + row) * DIM + (g & 7) * KCH + q * 8);
    };

    load_B(0); CP_COMMIT();   // group 0: A + B0
    load_B(1); CP_COMMIT();
    load_B(2); CP_COMMIT();
    CP_WAIT2();               // A + B0 complete for this thread
    __syncthreads();          // A visible block-wide

    // ---- per-group phase skew (~512 cyc per group index) ----
    {
        float zz = 1.0f + (float)grp;
#pragma unroll 1
        for (int i = 0; i < grp * 128; ++i)
            asm volatile("fma.rn.f32 %0, %0, 0f3F800001, 0f33800000;" : "+f"(zz));
        asm volatile("" :: "f"(zz));
    }

    float acc[4][4][4];
#pragma unroll
    for (int fi = 0; fi < 4; ++fi)
#pragma unroll
        for (int fj = 0; fj < 4; ++fj)
#pragma unroll
            for (int q = 0; q < 4; ++q) acc[fi][fj][q] = 0.f;

    const float INF = 3.402823466e38f;
    float rmin[8], xr[8];
#pragma unroll
    for (int i = 0; i < 8; ++i) rmin[i] = INF;
#pragma unroll
    for (int fi = 0; fi < 4; ++fi) {
        int r0 = b * NPTS + n0 + wn * 64 + fi * 16 + r4;
        xr[fi * 2 + 0] = g_xx[r0];
        xr[fi * 2 + 1] = g_xx[r0 + 8];
    }

#pragma unroll 1
    for (int g = 0; g < TOTSTG; ++g) {
        CP_WAIT2();
        GRP_BAR(grp + 1);

        const uint32_t a_base = sb + (uint32_t)(g & 7) * A_CHUNK + a_lane_base;
        const uint32_t b_ring = sb + B_OFF + (uint32_t)grp * B_GRP
                              + (uint32_t)(g & 3) * B_BUF + b_lane_base;

#pragma unroll
        for (int k16 = 0; k16 < 2; ++k16) {
            uint32_t af[4][4], bf0[4], bf1[4];
            LDSM_X4(bf0, b_ring + boff[k16]);
            LDSM_X4(bf1, b_ring + 1024 + boff[k16]);
#pragma unroll
            for (int fi = 0; fi < 4; ++fi)
                LDSM_X4(af[fi], a_base + fi * 1024 + aoff[k16]);
#pragma unroll
            for (int fi = 0; fi < 4; ++fi) {
                mma_f16(acc[fi][0][0], acc[fi][0][1], acc[fi][0][2], acc[fi][0][3],
                        af[fi][0], af[fi][1], af[fi][2], af[fi][3], bf0[0], bf0[1]);
                mma_f16(acc[fi][1][0], acc[fi][1][1], acc[fi][1][2], acc[fi][1][3],
                        af[fi][0], af[fi][1], af[fi][2], af[fi][3], bf0[2], bf0[3]);
                mma_f16(acc[fi][2][0], acc[fi][2][1], acc[fi][2][2], acc[fi][2][3],
                        af[fi][0], af[fi][1], af[fi][2], af[fi][3], bf1[0], bf1[1]);
                mma_f16(acc[fi][3][0], acc[fi][3][1], acc[fi][3][2], acc[fi][3][3],
                        af[fi][0], af[fi][1], af[fi][2], af[fi][3], bf1[2], bf1[3]);
            }
        }

        if (g + 3 < TOTSTG) load_B(g + 3);
        CP_COMMIT();

        // ---- per-tile epilogue (register-only) ----
        if ((g & 7) == 7) {
            const int m0t = m0bas + (g >> 3) * TILE_M;

            float yc[8];
#pragma unroll
            for (int fj = 0; fj < 4; ++fj) {
                int c0 = b * NPTS + m0t + wm * 32 + fj * 8 + 2 * c4;
                yc[fj * 2 + 0] = g_yy[c0];
                yc[fj * 2 + 1] = g_yy[c0 + 1];
            }

            float cmin[8];
#pragma unroll
            for (int i = 0; i < 8; ++i) cmin[i] = INF;

#pragma unroll
            for (int fi = 0; fi < 4; ++fi)
#pragma unroll
                for (int fj = 0; fj < 4; ++fj)
#pragma unroll
                    for (int r = 0; r < 2; ++r)
#pragma unroll
                        for (int c = 0; c < 2; ++c) {
                            float d = xr[fi * 2 + r] + yc[fj * 2 + c]
                                    - 2.0f * acc[fi][fj][2 * r + c];
                            rmin[fi * 2 + r] = fminf(rmin[fi * 2 + r], d);
                            cmin[fj * 2 + c] = fminf(cmin[fj * 2 + c], d);
                            acc[fi][fj][2 * r + c] = 0.f;
                        }

#pragma unroll
            for (int i = 0; i < 8; ++i) {
                cmin[i] = fminf(cmin[i], __shfl_xor_sync(0xFFFFFFFFu, cmin[i], 4));
                cmin[i] = fminf(cmin[i], __shfl_xor_sync(0xFFFFFFFFu, cmin[i], 8));
                cmin[i] = fminf(cmin[i], __shfl_xor_sync(0xFFFFFFFFu, cmin[i], 16));
            }
            if (r4 == 0) {
#pragma unroll
                for (int fj = 0; fj < 4; ++fj)
#pragma unroll
                    for (int c = 0; c < 2; ++c) {
                        int col = m0t + wm * 32 + fj * 8 + 2 * c4 + c;
                        atomicMin(&g_min_m[b * NPTS + col], f2ord(cmin[fj * 2 + c]));
                    }
            }
        }
    }

    // ---- final row-min flush ----
#pragma unroll
    for (int i = 0; i < 8; ++i) {
        rmin[i] = fminf(rmin[i], __shfl_xor_sync(0xFFFFFFFFu, rmin[i], 1));
        rmin[i] = fminf(rmin[i], __shfl_xor_sync(0xFFFFFFFFu, rmin[i], 2));
    }
    if (c4 == 0) {
#pragma unroll
        for (int fi = 0; fi < 4; ++fi)
#pragma unroll
            for (int r = 0; r < 2; ++r) {
                int row = n0 + wn * 64 + fi * 16 + 8 * r + r4;
                atomicMin(&g_min_n[b * NPTS + row], f2ord(rmin[fi * 2 + r]));
            }
    }

    // ---- fused finalize: last CTA reduces mins -> out[0] ----
    __shared__ unsigned s_last;
    __shared__ double   s_red[16];
    __threadfence();
    __syncthreads();
    if (tid == 0) {
        unsigned old = atomicAdd(&g_done, 1u);
        s_last = (old == (8u * 16u * BATCH - 1u)) ? 1u : 0u;
    }
    __syncthreads();
    if (s_last) {
        const int total = BATCH * NPTS;
        double s = 0.0;
        for (int i = tid; i < total; i += 512) s += (double)ord2f(__ldcg(&g_min_n[i]));
        for (int i = tid; i < total; i += 512) s += (double)ord2f(__ldcg(&g_min_m[i]));
#pragma unroll
        for (int off = 16; off > 0; off >>= 1)
            s += __shfl_xor_sync(0xFFFFFFFFu, s, off);
        if (lane == 0) s_red[wid] = s;
        __syncthreads();
        if (tid == 0) {
            double t = 0.0;
#pragma unroll
            for (int w = 0; w < 16; ++w) t += s_red[w];
            out[0] = (float)t;
            g_done = 0;
        }
    }
}

extern "C" void kernel_launch(void* const* d_in, const int* in_sizes, int n_in,
                              void* d_out, int out_size) {
    const float* gts   = (const float*)d_in[0];
    const float* preds = (const float*)d_in[1];
    float* out = (float*)d_out;

    cudaFuncSetAttribute(chamfer_mma_kernel,
                         cudaFuncAttributeMaxDynamicSharedMemorySize, SMEM_BYTES);

    dim3 gN((BATCH * NPTS) / 8, 2);
    norms_init_kernel<<<gN, 256>>>(gts, preds);

    dim3 gT(NPTS / (TILE_M * MT), NPTS / TILE_N, BATCH);
    chamfer_mma_kernel<<<gT, 512, SMEM_BYTES>>>(out);
}